// round 13
// baseline (speedup 1.0000x reference)
#include <cuda_runtime.h>
#include <cuda_bf16.h>
#include <float.h>
#include <math.h>

// Problem shape (fixed by reference setup_inputs)
#define B_   16
#define C_   256
#define H_   128
#define W_   128
#define HW_  (H_ * W_)           // 16384
#define HW4_ (HW_ / 4)           // 4096 float4 columns per image

// Q[kh][b][h][w]: 1-D conv contribution of feat row (h+kh-1) to output row h.
// Unique writer per slot (the k1 block owning that feat half-row).
__device__ float g_Q[3 * B_ * HW_];          // 3 MB
// E[side][kh][b*H+h]: boundary fix terms. side0 = missing kw=2 tap at w=63
// (produced by half1 from feat col 64); side1 = missing kw=0 tap at w=64
// (produced by half0 from feat col 63).
__device__ float g_E[2 * 3 * B_ * H_];

// ---------------------------------------------------------------------------
// Kernel 1: channel mean+max (R6 streaming body, byte-identical) + linear
// conv epilogue. Block = half-row (r, half): after the reduce, the half-row
// avg/max lives in padded smem; 64 threads compute the three 1-D row
// contributions and store to g_Q; one thread emits the boundary E terms.
// ---------------------------------------------------------------------------
__global__ __launch_bounds__(256) void reduce_conv_rows_kernel(
    const float* __restrict__ x,
    const float* __restrict__ conv_w)   // [1,2,3,3] OIHW
{
    cudaTriggerProgrammaticLaunchCompletion();

    __shared__ float4 s_sum[256];
    __shared__ float4 s_max[256];
    __shared__ float  s_f[2][66];        // padded half-row: [ch][1+64+1]
    __shared__ float  s_w[18];

    const int tid  = threadIdx.x;
    const int col  = tid & 15;                 // float4 column within half-row
    const int cs   = tid >> 4;                 // channel split 0..15

    const int blk    = blockIdx.x;             // 0..4095
    const int row_id = blk >> 1;               // 0..2047 == b*128 + h
    const int half   = blk & 1;
    const int b      = row_id >> 7;
    const int h      = row_id & 127;
    const int hw4    = (h << 5) + (half << 4) + col;

    if (tid < 18) s_w[tid] = __ldg(conv_w + tid);

    const float4* xb = reinterpret_cast<const float4*>(x)
                     + (size_t)b * C_ * HW4_ + (size_t)(cs * 16) * HW4_ + hw4;

    float4 s = make_float4(0.f, 0.f, 0.f, 0.f);
    float4 m = make_float4(-FLT_MAX, -FLT_MAX, -FLT_MAX, -FLT_MAX);

    #pragma unroll
    for (int c = 0; c < 16; ++c) {
        float4 v = __ldcs(xb + (size_t)c * HW4_);
        s.x += v.x; s.y += v.y; s.z += v.z; s.w += v.w;
        m.x = fmaxf(m.x, v.x); m.y = fmaxf(m.y, v.y);
        m.z = fmaxf(m.z, v.z); m.w = fmaxf(m.w, v.w);
    }

    s_sum[tid] = s;
    s_max[tid] = m;
    __syncthreads();

    if (tid < 16) {
        #pragma unroll
        for (int k = 1; k < 16; ++k) {
            float4 ps = s_sum[tid + k * 16];
            float4 pm = s_max[tid + k * 16];
            s.x += ps.x; s.y += ps.y; s.z += ps.z; s.w += ps.w;
            m.x = fmaxf(m.x, pm.x); m.y = fmaxf(m.y, pm.y);
            m.z = fmaxf(m.z, pm.z); m.w = fmaxf(m.w, pm.w);
        }
        const float inv = 1.0f / (float)C_;
        // padded smem: local col j -> index j+1
        s_f[0][1 + 4 * tid + 0] = s.x * inv;
        s_f[0][1 + 4 * tid + 1] = s.y * inv;
        s_f[0][1 + 4 * tid + 2] = s.z * inv;
        s_f[0][1 + 4 * tid + 3] = s.w * inv;
        s_f[1][1 + 4 * tid + 0] = m.x;
        s_f[1][1 + 4 * tid + 1] = m.y;
        s_f[1][1 + 4 * tid + 2] = m.z;
        s_f[1][1 + 4 * tid + 3] = m.w;
    }
    if (tid < 2) { s_f[tid][0] = 0.f; s_f[tid][65] = 0.f; }
    __syncthreads();

    // Epilogue A: 64 threads, one local output column each.
    if (tid < 64) {
        float q0 = 0.f, q1 = 0.f, q2 = 0.f;
        #pragma unroll
        for (int kw = 0; kw < 3; ++kw) {
            const float f0 = s_f[0][tid + kw];   // taps at padded idx tid..tid+2
            const float f1 = s_f[1][tid + kw];
            q0 = fmaf(f0, s_w[0 * 3 + kw], fmaf(f1, s_w[9 + 0 * 3 + kw], q0));
            q1 = fmaf(f0, s_w[1 * 3 + kw], fmaf(f1, s_w[9 + 1 * 3 + kw], q1));
            q2 = fmaf(f0, s_w[2 * 3 + kw], fmaf(f1, s_w[9 + 2 * 3 + kw], q2));
        }
        const int wg = (half << 6) + tid;        // global w of this column
        // contribution of feat row h (this block) to out row rt = h+1-kh
        if (h < H_ - 1) g_Q[(0 * B_ + b) * HW_ + (h + 1) * W_ + wg] = q0;
        g_Q[(1 * B_ + b) * HW_ + h * W_ + wg] = q1;
        if (h > 0)      g_Q[(2 * B_ + b) * HW_ + (h - 1) * W_ + wg] = q2;
    }

    // Epilogue B: boundary fix terms (one thread).
    if (tid == 64) {
        const int side = 1 - half;   // half0 -> side1 (fix w=64); half1 -> side0 (fix w=63)
        const int kw   = (side == 0) ? 2 : 0;
        const int eidx = (side == 0) ? 1 : 64;   // padded idx of the edge feat col
        const float e0 = s_f[0][eidx];
        const float e1 = s_f[1][eidx];
        #pragma unroll
        for (int kh = 0; kh < 3; ++kh) {
            const int rt = h + 1 - kh;
            if (rt < 0 || rt >= H_) continue;
            g_E[(side * 3 + kh) * B_ * H_ + b * H_ + rt] =
                e0 * s_w[kh * 3 + kw] + e1 * s_w[9 + kh * 3 + kw];
        }
    }
}

// ---------------------------------------------------------------------------
// Kernel 2: out = sigmoid(Q0+Q1+Q2 (+E at w=63/64)), 3 loads per pixel.
// 1024 blocks x 256 threads, PDL-overlapped.
// ---------------------------------------------------------------------------
__global__ __launch_bounds__(256) void sum_sigmoid_kernel(
    float* __restrict__ out)            // [B,1,H,W]
{
    cudaGridDependencySynchronize();

    const int idx = blockIdx.x * blockDim.x + threadIdx.x;  // 0 .. B*HW-1
    const int b  = idx >> 14;
    const int hw = idx & (HW_ - 1);
    const int h  = hw >> 7;
    const int w  = hw & (W_ - 1);

    const int base = b * HW_ + hw;
    float v = g_Q[1 * B_ * HW_ + base];
    if (h >= 1)      v += g_Q[0 * B_ * HW_ + base];
    if (h <= H_ - 2) v += g_Q[2 * B_ * HW_ + base];

    if (w == 63 || w == 64) {
        const int side = (w == 64);
        const int eb   = side * 3 * B_ * H_ + b * H_ + h;
        v += g_E[eb + 1 * B_ * H_];
        if (h >= 1)      v += g_E[eb + 0 * B_ * H_];
        if (h <= H_ - 2) v += g_E[eb + 2 * B_ * H_];
    }

    out[idx] = 1.0f / (1.0f + __expf(-v));
}

// ---------------------------------------------------------------------------
extern "C" void kernel_launch(void* const* d_in, const int* in_sizes, int n_in,
                              void* d_out, int out_size)
{
    const float* x      = (const float*)d_in[0];   // [16,256,128,128] f32
    const float* conv_w = (const float*)d_in[1];   // [1,2,3,3] f32
    float*       out    = (float*)d_out;           // [16,1,128,128] f32

    // Kernel 1: 4096 blocks x 256 threads (R6 streaming + conv epilogue)
    reduce_conv_rows_kernel<<<4096, 256>>>(x, conv_w);

    // Kernel 2: 1024 blocks x 256 threads, PDL-overlapped launch
    cudaLaunchConfig_t cfg = {};
    cfg.gridDim  = dim3((B_ * HW_) / 256, 1, 1);
    cfg.blockDim = dim3(256, 1, 1);
    cfg.dynamicSmemBytes = 0;
    cfg.stream = 0;

    cudaLaunchAttribute attrs[1];
    attrs[0].id = cudaLaunchAttributeProgrammaticStreamSerialization;
    attrs[0].val.programmaticStreamSerializationAllowed = 1;
    cfg.attrs = attrs;
    cfg.numAttrs = 1;

    cudaLaunchKernelEx(&cfg, sum_sigmoid_kernel, out);
}

// round 14
// speedup vs baseline: 1.0963x; 1.0963x over previous
#include <cuda_runtime.h>
#include <cuda_bf16.h>
#include <float.h>
#include <math.h>

// Problem shape (fixed by reference setup_inputs)
#define B_   16
#define C_   256
#define H_   128
#define W_   128
#define HW_  (H_ * W_)           // 16384
#define HW4_ (HW_ / 4)           // 4096 float4 columns per image

// Scratch: feat [B, 2, H, W]  (avg then max)
__device__ float g_feat[B_ * 2 * HW_];

// MUFU-free sigmoid: exp2 poly + exponent bit-trick, Newton reciprocal.
// All FMA/ALU pipe -> avoids the 0.5 op/cyc/SM MUFU ceiling that binds the
// exposed tail. |rel err| ~1e-7.
__device__ __forceinline__ float fast_sigmoid(float x)
{
    // sigmoid(x) = 1 / (1 + 2^(-x*log2(e)))
    float y = -x * 1.4426950408889634f;
    y = fminf(fmaxf(y, -126.0f), 126.0f);
    float n = floorf(y);
    float f = y - n;                         // f in [0,1)
    // 2^f, degree-5 minimax (Cephes-style), rel err ~2e-8
    float p = 1.3333558146428443e-3f;
    p = fmaf(p, f, 9.8105352697968360e-3f);
    p = fmaf(p, f, 5.5518340325804030e-2f);
    p = fmaf(p, f, 2.4017933341410937e-1f);
    p = fmaf(p, f, 6.9314692312196549e-1f);
    p = fmaf(p, f, 1.0f);
    const int ni = (int)n;                   // exact (n integral, |n|<=126)
    const float s = __int_as_float((ni + 127) << 23);   // 2^n
    const float t = s * p;                   // 2^y = e^(-x)
    // r = 1/(1+t): bit-trick seed + 3 Newton iterations (FMA only)
    const float u = 1.0f + t;
    float r = __uint_as_float(0x7EF311C3u - __float_as_uint(u));
    r = r * (2.0f - u * r);
    r = r * (2.0f - u * r);
    r = r * (2.0f - u * r);
    return r;
}

// ---------------------------------------------------------------------------
// Kernel 1: channel-wise mean + max over C=256.  (R6 config — best measured,
// byte-identical: 4096 blocks x 256 thr, half-row x 16 splits, full unroll)
// ---------------------------------------------------------------------------
__global__ __launch_bounds__(256) void reduce_mean_max_kernel(
    const float* __restrict__ x)
{
    cudaTriggerProgrammaticLaunchCompletion();

    __shared__ float4 s_sum[256];
    __shared__ float4 s_max[256];

    const int tid  = threadIdx.x;
    const int col  = tid & 15;                 // float4 column within half-row
    const int cs   = tid >> 4;                 // channel split 0..15

    const int blk    = blockIdx.x;             // 0..4095
    const int row_id = blk >> 1;               // 0..2047 == b*128 + h
    const int half   = blk & 1;
    const int b      = row_id >> 7;
    const int h      = row_id & 127;
    const int hw4    = (h << 5) + (half << 4) + col;

    const float4* xb = reinterpret_cast<const float4*>(x)
                     + (size_t)b * C_ * HW4_ + (size_t)(cs * 16) * HW4_ + hw4;

    float4 s = make_float4(0.f, 0.f, 0.f, 0.f);
    float4 m = make_float4(-FLT_MAX, -FLT_MAX, -FLT_MAX, -FLT_MAX);

    #pragma unroll
    for (int c = 0; c < 16; ++c) {
        float4 v = __ldcs(xb + (size_t)c * HW4_);
        s.x += v.x; s.y += v.y; s.z += v.z; s.w += v.w;
        m.x = fmaxf(m.x, v.x); m.y = fmaxf(m.y, v.y);
        m.z = fmaxf(m.z, v.z); m.w = fmaxf(m.w, v.w);
    }

    s_sum[tid] = s;
    s_max[tid] = m;
    __syncthreads();

    if (tid < 16) {
        #pragma unroll
        for (int k = 1; k < 16; ++k) {
            float4 ps = s_sum[tid + k * 16];
            float4 pm = s_max[tid + k * 16];
            s.x += ps.x; s.y += ps.y; s.z += ps.z; s.w += ps.w;
            m.x = fmaxf(m.x, pm.x); m.y = fmaxf(m.y, pm.y);
            m.z = fmaxf(m.z, pm.z); m.w = fmaxf(m.w, pm.w);
        }
        const float inv = 1.0f / (float)C_;
        float4 a = make_float4(s.x * inv, s.y * inv, s.z * inv, s.w * inv);

        float4* fa = reinterpret_cast<float4*>(g_feat)
                   + (size_t)b * 2 * HW4_ + hw4;
        fa[0]    = a;   // channel 0: avg
        fa[HW4_] = m;   // channel 1: max
    }
}

// ---------------------------------------------------------------------------
// Kernel 2: 3x3 conv (2 in ch, 1 out ch, pad 1, no bias) + MUFU-free sigmoid.
// 1024 blocks x 256 thr, 1 px/thread (R6-proven). PDL overlapped.
// ---------------------------------------------------------------------------
__global__ __launch_bounds__(256) void conv_sigmoid_kernel(
    const float* __restrict__ conv_w,   // [1,2,3,3] OIHW
    float* __restrict__ out)            // [B,1,H,W]
{
    const int idx = blockIdx.x * blockDim.x + threadIdx.x;  // 0 .. B*HW-1
    const int b  = idx >> 14;           // / HW_
    const int hw = idx & (HW_ - 1);
    const int h  = hw >> 7;             // / W_
    const int w  = hw & (W_ - 1);

    // Prologue (overlaps producer drain): weights into registers.
    float wk[18];
    #pragma unroll
    for (int i = 0; i < 18; ++i) wk[i] = __ldg(conv_w + i);

    cudaGridDependencySynchronize();

    const float* f0 = g_feat + (size_t)b * 2 * HW_;   // avg channel
    const float* f1 = f0 + HW_;                       // max channel

    float acc = 0.f;
    #pragma unroll
    for (int kh = 0; kh < 3; ++kh) {
        const int hh = h + kh - 1;
        if (hh < 0 || hh >= H_) continue;
        #pragma unroll
        for (int kw = 0; kw < 3; ++kw) {
            const int ww = w + kw - 1;
            if (ww < 0 || ww >= W_) continue;
            const int off = hh * W_ + ww;
            acc = fmaf(f0[off], wk[kh * 3 + kw], acc);
            acc = fmaf(f1[off], wk[9 + kh * 3 + kw], acc);
        }
    }

    out[idx] = fast_sigmoid(acc);
}

// ---------------------------------------------------------------------------
extern "C" void kernel_launch(void* const* d_in, const int* in_sizes, int n_in,
                              void* d_out, int out_size)
{
    const float* x      = (const float*)d_in[0];   // [16,256,128,128] f32
    const float* conv_w = (const float*)d_in[1];   // [1,2,3,3] f32
    float*       out    = (float*)d_out;           // [16,1,128,128] f32

    // Kernel 1: 4096 blocks x 256 threads (R6 best)
    reduce_mean_max_kernel<<<4096, 256>>>(x);

    // Kernel 2: 1024 blocks x 256 threads, PDL-overlapped launch
    cudaLaunchConfig_t cfg = {};
    cfg.gridDim  = dim3((B_ * HW_) / 256, 1, 1);
    cfg.blockDim = dim3(256, 1, 1);
    cfg.dynamicSmemBytes = 0;
    cfg.stream = 0;

    cudaLaunchAttribute attrs[1];
    attrs[0].id = cudaLaunchAttributeProgrammaticStreamSerialization;
    attrs[0].val.programmaticStreamSerializationAllowed = 1;
    cfg.attrs = attrs;
    cfg.numAttrs = 1;

    cudaLaunchKernelEx(&cfg, conv_sigmoid_kernel, conv_w, out);
}